// round 5
// baseline (speedup 1.0000x reference)
#include <cuda_runtime.h>
#include <cuda_fp16.h>
#include <cstdint>

#define G     128
#define GG    (G*G)
#define RS    130              // padded row stride in halfs (65 half2 -> conflict-free-ish)
#define RS2   65               // row stride in half2
#define NL    200000
#define HALF  200.0f
#define DX    3.125f
#define INVDX 0.32f
#define DX2   9.765625f
#define TWODX2 19.53125f
// C2LOG = ICC * log2(e) = (2/(9*pi)) * 1.4426950409
#define C2LOG 0.1020498f
#define KW2   28.2743338823f   // 9*pi
#define TFRAC 0.2016f
#define THREADS 512
#define LPT   4
#define LPC   (THREADS*LPT)            // 2048
#define NCTA  ((NL + LPC - 1)/LPC)     // 98 per axis

#define SLICE_BYTES  (G*RS*2)          // 33280
#define SMEM_BYTES   (128 + 2*SLICE_BYTES)

// fp16 slice-major padded volumes, one per axis
__device__ __half g_tx[G*G*RS];
__device__ __half g_ty[G*G*RS];
__device__ __half g_tz[G*G*RS];

// One fused transform: read image[i][j][k] tile once, emit all three layouts.
//  g_tx[(i*G + j)*RS + k] = img[i][j][k]   (direct)
//  g_ty[(j*G + i)*RS + k] = img[i][j][k]   (direct)
//  g_tz[(k*G + i)*RS + j] = img[i][j][k]   (j/k transpose via smem tile)
__global__ void trans_all_kernel(const float* __restrict__ img) {
    __shared__ float tile[32][33];
    const int i  = blockIdx.z;
    const int jb = blockIdx.x * 32;
    const int kb = blockIdx.y * 32;
    const int tx = threadIdx.x, ty = threadIdx.y;   // (32, 8)
    #pragma unroll
    for (int r = 0; r < 32; r += 8) {
        const int j = jb + ty + r;
        const float v = img[(i*G + j)*G + kb + tx];
        tile[ty + r][tx] = v;
        const __half h = __float2half(v);
        g_tx[(i*G + j)*RS + kb + tx] = h;
        g_ty[(j*G + i)*RS + kb + tx] = h;
    }
    __syncthreads();
    #pragma unroll
    for (int r = 0; r < 32; r += 8)
        g_tz[((kb + ty + r)*G + i)*RS + jb + tx] = __float2half(tile[tx][ty + r]);
}

// ---------------- TMA / mbarrier helpers ----------------
__device__ __forceinline__ void mbar_init(uint32_t mbar, uint32_t count) {
    asm volatile("mbarrier.init.shared::cta.b64 [%0], %1;" :: "r"(mbar), "r"(count) : "memory");
}
__device__ __forceinline__ void mbar_expect_tx(uint32_t mbar, uint32_t bytes) {
    asm volatile("mbarrier.arrive.expect_tx.shared::cta.b64 _, [%0], %1;"
                 :: "r"(mbar), "r"(bytes) : "memory");
}
__device__ __forceinline__ void mbar_wait(uint32_t mbar, uint32_t phase) {
    asm volatile(
        "{\n\t"
        ".reg .pred P1;\n\t"
        "LAB_WAIT_%=:\n\t"
        "mbarrier.try_wait.parity.acquire.cta.shared::cta.b64 P1, [%0], %1, 0x989680;\n\t"
        "@P1 bra LAB_DONE_%=;\n\t"
        "bra.uni LAB_WAIT_%=;\n\t"
        "LAB_DONE_%=:\n\t"
        "}"
        :: "r"(mbar), "r"(phase) : "memory");
}
__device__ __forceinline__ void bulk_g2s(uint32_t dst, const void* src, uint32_t bytes, uint32_t mbar) {
    asm volatile("cp.async.bulk.shared::cluster.global.mbarrier::complete_tx::bytes [%0], [%1], %2, [%3];"
                 :: "r"(dst), "l"(src), "r"(bytes), "r"(mbar) : "memory");
}

__global__ __launch_bounds__(THREADS, 2)
void proj_kernel(const float* __restrict__ lx,
                 const float* __restrict__ ly,
                 const float* __restrict__ lz,
                 float* __restrict__ out)
{
    extern __shared__ __align__(128) unsigned char smem_raw[];
    const uint32_t smem_base = (uint32_t)__cvta_generic_to_shared(smem_raw);
    const uint32_t mbar0 = smem_base;
    __half* sbuf = (__half*)(smem_raw + 128);

    const int axis = blockIdx.y;
    const int tid  = threadIdx.x;
    const int cta_base = blockIdx.x * LPC;

    const float* lors;
    const __half* vol;
    int q0, q1;
    if (axis == 0)      { lors = lx; vol = g_tx; q0 = 1; q1 = 2; }
    else if (axis == 1) { lors = ly; vol = g_ty; q0 = 0; q1 = 2; }
    else                { lors = lz; vol = g_tz; q0 = 0; q1 = 1; }

    // per-LOR params. lors scan-axis coords are exactly -HALF/+HALF -> dvz = 400,
    // t_k = (k+0.5)*DX/400 is LOR-independent.
    float P0x[LPT], P0y[LPT], dvx[LPT], dvy[LPT], total[LPT];
    #pragma unroll
    for (int l = 0; l < LPT; l++) {
        int gi = cta_base + l*THREADS + tid;
        int lr = gi < NL ? gi : NL - 1;
        const float* L6 = lors + lr * 6;
        P0x[l] = L6[q0]; P0y[l] = L6[q1];
        dvx[l] = L6[q0+3] - P0x[l];
        dvy[l] = L6[q1+3] - P0y[l];
        total[l] = 0.0f;
    }

    const __half2 nCh2 = __float2half2_rn(-C2LOG);
    const __half2 zero2 = __float2half2_rn(0.0f);

    if (tid == 0) {
        mbar_init(mbar0,     1);
        mbar_init(mbar0 + 8, 1);
        asm volatile("fence.proxy.async.shared::cta;" ::: "memory");
    }
    __syncthreads();
    if (tid == 0) {
        mbar_expect_tx(mbar0,     SLICE_BYTES);
        bulk_g2s(smem_base + 128,               vol,          SLICE_BYTES, mbar0);
        mbar_expect_tx(mbar0 + 8, SLICE_BYTES);
        bulk_g2s(smem_base + 128 + SLICE_BYTES, vol + G*RS,   SLICE_BYTES, mbar0 + 8);
    }

    for (int k = 0; k < G; k++) {
        const int b = k & 1;
        mbar_wait(mbar0 + b*8, (k >> 1) & 1);
        const __half2* slice = (const __half2*)(sbuf + b * (G*RS));

        const float tk = ((float)k + 0.5f) * (DX / 400.0f);

        #pragma unroll
        for (int l = 0; l < LPT; l++) {
            const float xc = fmaf(tk, dvx[l], P0x[l]);
            const float yc = fmaf(tk, dvy[l], P0y[l]);

            // anchors: alo = floor(ux - TFRAC) - 1, clamped
            const float ux = fmaf(xc, INVDX, HALF*INVDX);
            int alo = __float2int_rd(ux - TFRAC) - 1;
            alo = min(max(alo, 0), G - 4);
            const float uy = fmaf(yc, INVDX, HALF*INVDX);
            int clo = __float2int_rd(uy - TFRAC) - 1;
            clo = min(max(clo, 0), G - 6);
            const int cE = clo & ~1;

            const float sx0 = fmaf((float)alo, DX, 0.5f*DX - HALF) - xc;
            const float sy0 = fmaf((float)cE,  DX, 0.5f*DX - HALF) - yc;

            // column sy^2 chain (float), packed to half2 pairs
            const float q0f = sy0 * sy0;
            float u = fmaf(2.0f*DX, sy0, DX2);
            const float q1f = q0f + u; u += TWODX2;
            const float q2f = q1f + u; u += TWODX2;
            const float q3f = q2f + u; u += TWODX2;
            const float q4f = q3f + u; u += TWODX2;
            const float q5f = q4f + u;
            const __half2 S0 = __floats2half2_rn(q0f, q1f);
            const __half2 S1 = __floats2half2_rn(q2f, q3f);
            const __half2 S2 = __floats2half2_rn(q4f, q5f);
            const __half2 P0 = h2exp2(__hmul2(S0, nCh2));
            const __half2 P1 = h2exp2(__hmul2(S1, nCh2));
            const __half2 P2 = h2exp2(__hmul2(S2, nCh2));

            // row sx^2 chain (float)
            float px = sx0 * sx0;
            float vx = fmaf(2.0f*DX, sx0, DX2);

            const __half2* rp = slice + alo * RS2 + (cE >> 1);
            __half2 acc2 = zero2;

            #pragma unroll
            for (int a = 0; a < 4; a++) {
                const __half2 V0 = rp[0];
                const __half2 V1 = rp[1];
                const __half2 V2 = rp[2];

                const __half2 lim2 = __float2half2_rn(KW2 - px);
                const __half2 wx2  = __float2half2_rn(exp2f(-C2LOG * px));

                __half2 r2 = __hmul2(__hmul2(__hle2(S0, lim2), P0), V0);
                r2 = __hfma2(__hmul2(__hle2(S1, lim2), P1), V1, r2);
                r2 = __hfma2(__hmul2(__hle2(S2, lim2), P2), V2, r2);
                acc2 = __hfma2(wx2, r2, acc2);

                px += vx; vx += TWODX2;
                rp += RS2;
            }

            const float2 f2 = __half22float2(acc2);
            total[l] += f2.x + f2.y;
        }

        __syncthreads();
        if (tid == 0 && k + 2 < G) {
            mbar_expect_tx(mbar0 + b*8, SLICE_BYTES);
            bulk_g2s(smem_base + 128 + b*SLICE_BYTES,
                     vol + (size_t)(k+2)*(G*RS), SLICE_BYTES, mbar0 + b*8);
        }
    }

    #pragma unroll
    for (int l = 0; l < LPT; l++) {
        int gi = cta_base + l*THREADS + tid;
        if (gi < NL) {
            float Ln = sqrtf(fmaf(dvx[l], dvx[l], fmaf(dvy[l], dvy[l], 160000.0f)));
            out[axis * NL + gi] = total[l] * (DX / 400.0f) * Ln;
        }
    }
}

extern "C" void kernel_launch(void* const* d_in, const int* in_sizes, int n_in,
                              void* d_out, int out_size)
{
    (void)in_sizes; (void)n_in; (void)out_size;
    const float* image = (const float*)d_in[0];
    const float* xl    = (const float*)d_in[1];
    const float* yl    = (const float*)d_in[2];
    const float* zl    = (const float*)d_in[3];
    float* out = (float*)d_out;

    static bool attr_set = false;
    if (!attr_set) {
        cudaFuncSetAttribute(proj_kernel, cudaFuncAttributeMaxDynamicSharedMemorySize, SMEM_BYTES);
        attr_set = true;
    }

    trans_all_kernel<<<dim3(4, 4, G), dim3(32, 8)>>>(image);

    dim3 grid(NCTA, 3);
    proj_kernel<<<grid, THREADS, SMEM_BYTES>>>(xl, yl, zl, out);
}